// round 2
// baseline (speedup 1.0000x reference)
#include <cuda_runtime.h>
#include <cstdint>

#define C0 32
#define C1 16
#define FTOT 80
#define NSS 528
#define NTERMS 664
#define NITER 21          // ceil(664/32)
#define WARPS 8
#define NTHREADS 256

// selu / math constants
#define SELU_SCALE 1.0507009873554805f
#define SELU_ALPHA 1.6732632423543772f
#define L2E        1.4426950408889634f
#define RSQRT3     0.57735026918962576f

__device__ __forceinline__ float ex2f(float x) {
    float y;
    asm("ex2.approx.ftz.f32 %0, %1;" : "=f"(y) : "f"(x));
    return y;
}

__global__ __launch_bounds__(NTHREADS)
void gap_kernel(const float* __restrict__ ft, const int* __restrict__ bidx,
                const float* __restrict__ W, float* __restrict__ out, int N)
{
    __shared__ float s_nb [WARPS][FTOT];   // raw node features (operand i)
    __shared__ float s_nbs[WARPS][FTOT];   // pre-scaled copy (operand j): s*L2E, v*RSQRT3*L2E
    __shared__ float s_acc[FTOT];
    __shared__ float s_z;
    __shared__ int   s_seg[2];

    const int tid  = threadIdx.x;
    const int wid  = tid >> 5;
    const int lane = tid & 31;
    const int g    = blockIdx.x;

    if (tid < FTOT) s_acc[tid] = 0.f;
    if (tid == 0)   s_z = 0.f;
    if (tid < 2) {
        // lower_bound of (g + tid) in sorted batch_index
        int target = g + tid;
        int lo = 0, hi = N;
        while (lo < hi) {
            int mid = (lo + hi) >> 1;
            lo = (bidx[mid] < target) ? mid + 1 : lo;
            hi = (bidx[mid] < target) ? hi : mid;
        }
        s_seg[tid] = lo;
    }

    // ---- per-lane term table, once per block, kept in registers ----
    // term k handled by lane (k%32) at unrolled step t=k/32.
    // off[t]: packed byte offsets of operand i (raw copy) and j (scaled copy).
    //
    // selu(p) = SC*max(p,0) + SC*SA*(exp(min(p,0)) - 1)
    // With pl = p*L2E staged via the smem scaling, and wk = (SC/L2E)*w:
    //   xh += wk*max(pl,0)          -> SC*w*max(p,0)
    //   xe += wk*ex2(min(pl,0))     -> (SC/L2E)*w*exp(min(p,0))
    //   x   = xh + (SA*L2E)*xe - SC*SA*sum(w)
    float wk [NITER];
    int   off[NITER];
    float csum = 0.f;
#pragma unroll
    for (int t = 0; t < NITER; ++t) {
        int k = lane + 32 * t;
        float w = 0.f; int oi = 0, oj = 0;
        if (k < NTERMS) {
            w = __ldg(&W[k]);
            if (k < NSS) {                    // triu of 32x32, row-major
                int kk = k, i = 0;
                while (kk >= C0 - i) { kk -= C0 - i; ++i; }
                int j = i + kk;
                oi = i * 4; oj = j * 4;
            } else {                           // triu of 16x16 over v-dots
                int kk = k - NSS, i = 0;
                while (kk >= C1 - i) { kk -= C1 - i; ++i; }
                int j = i + kk;
                oi = (C0 + 3 * i) * 4; oj = (C0 + 3 * j) * 4;
            }
        }
        wk[t]  = (SELU_SCALE / L2E) * w;
        off[t] = oi | (oj << 16);
        csum  += w;
    }
    const float c_lane = -SELU_SCALE * SELU_ALPHA * csum;   // FIX: include SC factor

    __syncthreads();
    const int start = s_seg[0], end = s_seg[1];

    const char* nbb  = (const char*)s_nb[wid];
    const char* nbsb = (const char*)s_nbs[wid];

    float a0 = 0.f, a1 = 0.f, a2 = 0.f, zacc = 0.f;

    for (int n = start + wid; n < end; n += WARPS) {
        const float* p = ft + (size_t)n * FTOT;
        float f0 = p[lane];
        float f1 = p[lane + 32];
        float f2 = (lane < 16) ? p[lane + 64] : 0.f;
        s_nb [wid][lane]      = f0;
        s_nb [wid][lane + 32] = f1;
        s_nbs[wid][lane]      = f0 * L2E;                 // s region
        s_nbs[wid][lane + 32] = f1 * (RSQRT3 * L2E);      // v region
        if (lane < 16) {
            s_nb [wid][lane + 64] = f2;
            s_nbs[wid][lane + 64] = f2 * (RSQRT3 * L2E);
        }
        __syncwarp();

        float xh = 0.f, xe = 0.f;
#pragma unroll
        for (int t = 0; t < NITER; ++t) {
            int k = lane + 32 * t;      // compile-time t: branch uniform except t==16
            int o  = off[t];
            int oi = o & 0xFFFF, oj = o >> 16;
            float pl;
            if (k < NSS) {
                pl = *(const float*)(nbb + oi) * *(const float*)(nbsb + oj);
            } else {
                pl =       *(const float*)(nbb + oi)     * *(const float*)(nbsb + oj);
                pl = fmaf( *(const float*)(nbb + oi + 4), *(const float*)(nbsb + oj + 4), pl);
                pl = fmaf( *(const float*)(nbb + oi + 8), *(const float*)(nbsb + oj + 8), pl);
            }
            float hi = fmaxf(pl, 0.f);
            float lo = fminf(pl, 0.f);
            float e  = ex2f(lo);              // = exp(min(p,0)), L2E pre-folded
            xh = fmaf(wk[t], hi, xh);
            xe = fmaf(wk[t], e,  xe);
        }
        float x = fmaf(SELU_ALPHA * L2E, xe, xh) + c_lane;   // FIX: SC folded via wk
#pragma unroll
        for (int o2 = 16; o2; o2 >>= 1)
            x += __shfl_xor_sync(0xFFFFFFFFu, x, o2);

        float ex = ex2f(x * L2E);             // exp(x)
        zacc += ex;
        a0 = fmaf(ex, f0, a0);
        a1 = fmaf(ex, f1, a1);
        a2 = fmaf(ex, f2, a2);
        __syncwarp();                          // protect smem tile before next overwrite
    }

    atomicAdd(&s_acc[lane],      a0);
    atomicAdd(&s_acc[lane + 32], a1);
    if (lane < 16) atomicAdd(&s_acc[lane + 64], a2);
    if (lane == 0) atomicAdd(&s_z, zacc);
    __syncthreads();

    float z   = s_z;
    float inv = (z != 0.f) ? (1.0f / z) : 0.f;   // empty graph -> zeros
    for (int f = tid; f < FTOT; f += NTHREADS)
        out[(size_t)g * FTOT + f] = s_acc[f] * inv;
}

extern "C" void kernel_launch(void* const* d_in, const int* in_sizes, int n_in,
                              void* d_out, int out_size)
{
    // Robust input identification:
    //  node_ft: largest buffer (N*80 fp32); batch_index: size N int32;
    //  W: size 664; num_graphs scalar ignored (derive NG from out_size).
    int ftIdx = -1; long ftSize = -1;
    for (int i = 0; i < n_in; ++i)
        if ((long)in_sizes[i] > ftSize) { ftSize = in_sizes[i]; ftIdx = i; }
    const int N = (int)(ftSize / FTOT);

    int biIdx = -1, wIdx = -1;
    for (int i = 0; i < n_in; ++i) {
        if (i == ftIdx) continue;
        if (in_sizes[i] == N)       biIdx = i;
        else if (in_sizes[i] == NTERMS) wIdx = i;
    }

    const float* ft   = (const float*)d_in[ftIdx];
    const int*   bidx = (const int*)  d_in[biIdx];
    const float* W    = (const float*)d_in[wIdx];
    float*       out  = (float*)d_out;
    const int    NG   = out_size / FTOT;

    gap_kernel<<<NG, NTHREADS>>>(ft, bidx, W, out, N);
}

// round 3
// speedup vs baseline: 2.1675x; 2.1675x over previous
#include <cuda_runtime.h>
#include <cstdint>

#define C0 32
#define C1 16
#define FTOT 80
#define NSS 528
#define NTERMS 664
#define NMAX 400000

#define SELU_SCALE 1.0507009873554805f
#define SELU_ALPHA 1.6732632423543772f
#define L2E        1.4426950408889634f
#define SQRT_L2E   1.2011224087864498f   /* sqrt(log2 e)            */
#define SQRT_VL2E  0.9126556632464995f   /* sqrt(log2(e)/sqrt(3))   */

// triu(row-major) flat index, compile-time
#define KS(i,j) ((i)*C0 - (i)*((i)-1)/2 + ((j)-(i)))
#define KV(i,j) (NSS + (i)*C1 - (i)*((i)-1)/2 + ((j)-(i)))

__constant__ float cW[NTERMS];
__device__ float   g_c2;
__device__ float   g_ex[NMAX];

__device__ __forceinline__ float ex2f(float x) {
    float y;
    asm("ex2.approx.ftz.f32 %0, %1;" : "=f"(y) : "f"(x));
    return y;
}

// ---- prep: c2 = -SC*SA*L2E * sum(W) ----
__global__ void prep_kernel(const float* __restrict__ W) {
    float s = 0.f;
    for (int k = threadIdx.x; k < NTERMS; k += 32) s += W[k];
#pragma unroll
    for (int o = 16; o; o >>= 1) s += __shfl_xor_sync(0xFFFFFFFFu, s, o);
    if (threadIdx.x == 0) g_c2 = -SELU_SCALE * SELU_ALPHA * L2E * s;
}

// ---- phase 1: per-node attention logit -> ex[n]; node-per-lane, all-register ----
__global__ __launch_bounds__(256)
void phase1(const float* __restrict__ ft, int N)
{
    const int n = blockIdx.x * 256 + threadIdx.x;
    if (n >= N) return;
    const float4* p = (const float4*)(ft + (size_t)n * FTOT);

    float xh = 0.f, xe = 0.f;

    {   // scalar-scalar terms: p_ij = s_i*s_j, s pre-scaled by sqrt(L2E)
        float s[C0];
#pragma unroll
        for (int q = 0; q < 8; ++q) {
            float4 t = __ldg(p + q);
            s[4*q+0] = t.x * SQRT_L2E; s[4*q+1] = t.y * SQRT_L2E;
            s[4*q+2] = t.z * SQRT_L2E; s[4*q+3] = t.w * SQRT_L2E;
        }
#pragma unroll
        for (int i = 0; i < C0; ++i)
#pragma unroll
            for (int j = i; j < C0; ++j) {
                float pl = s[i] * s[j];               // = L2E * p
                float w  = cW[KS(i, j)];              // uniform LDCU
                xh = fmaf(w, fmaxf(pl, 0.f), xh);
                xe = fmaf(w, ex2f(fminf(pl, 0.f)), xe);
            }
    }
    {   // vector-vector terms: p_ij = (v_i . v_j)/sqrt(3), scaled into loads
        float v[3 * C1];
#pragma unroll
        for (int q = 0; q < 12; ++q) {
            float4 t = __ldg(p + 8 + q);
            v[4*q+0] = t.x * SQRT_VL2E; v[4*q+1] = t.y * SQRT_VL2E;
            v[4*q+2] = t.z * SQRT_VL2E; v[4*q+3] = t.w * SQRT_VL2E;
        }
#pragma unroll
        for (int i = 0; i < C1; ++i)
#pragma unroll
            for (int j = i; j < C1; ++j) {
                float pl = v[3*i] * v[3*j];
                pl = fmaf(v[3*i+1], v[3*j+1], pl);
                pl = fmaf(v[3*i+2], v[3*j+2], pl);
                float w = cW[KV(i, j)];
                xh = fmaf(w, fmaxf(pl, 0.f), xh);
                xe = fmaf(w, ex2f(fminf(pl, 0.f)), xe);
            }
    }
    // exp(x) = ex2( SC*(xh + SA*L2E*xe) + c2 )
    float earg = fmaf(SELU_SCALE, fmaf(SELU_ALPHA * L2E, xe, xh), g_c2);
    g_ex[n] = ex2f(earg);
}

// ---- phase 2: per-graph weighted segment sum + normalize ----
__global__ __launch_bounds__(256)
void phase2(const float* __restrict__ ft, const int* __restrict__ bidx,
            float* __restrict__ out, int N)
{
    __shared__ float s_acc[FTOT];
    __shared__ float s_z;
    __shared__ int   s_seg[2];

    const int tid  = threadIdx.x;
    const int wid  = tid >> 5;
    const int lane = tid & 31;
    const int g    = blockIdx.x;

    if (tid < FTOT) s_acc[tid] = 0.f;
    if (tid == 0)   s_z = 0.f;
    if (tid < 2) {
        int target = g + tid;
        int lo = 0, hi = N;
        while (lo < hi) {
            int mid = (lo + hi) >> 1;
            bool lt = (bidx[mid] < target);
            lo = lt ? mid + 1 : lo;
            hi = lt ? hi : mid;
        }
        s_seg[tid] = lo;
    }
    __syncthreads();
    const int start = s_seg[0], end = s_seg[1];

    float a0 = 0.f, a1 = 0.f, a2 = 0.f, zacc = 0.f;
    for (int n = start + wid; n < end; n += 8) {
        const float* p = ft + (size_t)n * FTOT;
        float ex = __ldg(&g_ex[n]);
        a0 = fmaf(ex, p[lane],      a0);
        a1 = fmaf(ex, p[lane + 32], a1);
        if (lane < 16) a2 = fmaf(ex, p[lane + 64], a2);
        zacc += ex;                 // same per lane; only lane0's copy is used
    }
    atomicAdd(&s_acc[lane],      a0);
    atomicAdd(&s_acc[lane + 32], a1);
    if (lane < 16) atomicAdd(&s_acc[lane + 64], a2);
    if (lane == 0) atomicAdd(&s_z, zacc);
    __syncthreads();

    float z   = s_z;
    float inv = (z != 0.f) ? (1.0f / z) : 0.f;   // empty graph -> zeros
    if (tid < FTOT) out[(size_t)g * FTOT + tid] = s_acc[tid] * inv;
}

extern "C" void kernel_launch(void* const* d_in, const int* in_sizes, int n_in,
                              void* d_out, int out_size)
{
    // node_ft: largest buffer; batch_index: size N int32; W: size 664.
    int ftIdx = -1; long ftSize = -1;
    for (int i = 0; i < n_in; ++i)
        if ((long)in_sizes[i] > ftSize) { ftSize = in_sizes[i]; ftIdx = i; }
    const int N = (int)(ftSize / FTOT);

    int biIdx = -1, wIdx = -1;
    for (int i = 0; i < n_in; ++i) {
        if (i == ftIdx) continue;
        if (in_sizes[i] == N)            biIdx = i;
        else if (in_sizes[i] == NTERMS)  wIdx = i;
    }

    const float* ft   = (const float*)d_in[ftIdx];
    const int*   bidx = (const int*)  d_in[biIdx];
    const float* W    = (const float*)d_in[wIdx];
    float*       out  = (float*)d_out;
    const int    NG   = out_size / FTOT;

    cudaMemcpyToSymbolAsync(cW, W, NTERMS * sizeof(float), 0,
                            cudaMemcpyDeviceToDevice, 0);
    prep_kernel<<<1, 32>>>(W);
    phase1<<<(N + 255) / 256, 256>>>(ft, N);
    phase2<<<NG, 256>>>(ft, bidx, out, N);
}

// round 4
// speedup vs baseline: 2.2257x; 1.0269x over previous
#include <cuda_runtime.h>
#include <cstdint>

#define C0 32
#define C1 16
#define FTOT 80
#define NSS 528
#define NTERMS 664
#define NMAX 400000

#define SELU_SCALE 1.0507009873554805f
#define SELU_ALPHA 1.6732632423543772f
#define L2E        1.4426950408889634f
#define SQRT_L2E   1.2011224087864498f   /* sqrt(log2 e)            */
#define SQRT_VL2E  0.9126556632464995f   /* sqrt(log2(e)/sqrt(3))   */

// triu(row-major) flat index, compile-time
#define KS(i,j) ((i)*C0 - (i)*((i)-1)/2 + ((j)-(i)))
#define KV(i,j) (NSS + (i)*C1 - (i)*((i)-1)/2 + ((j)-(i)))

__constant__ float cW[NTERMS];
__device__ float   g_ex[NMAX];

__device__ __forceinline__ float ex2f(float x) {
    float y;
    asm("ex2.approx.ftz.f32 %0, %1;" : "=f"(y) : "f"(x));
    return y;
}

// ---- phase 1: per-node attention logit -> ex[n]; node-per-lane, all-register ----
// Softmax shift invariance: the constant -SC*SA*sum(W) term of selu's negative
// branch cancels in ex/z, so it is omitted entirely (no prep kernel needed).
__global__ __launch_bounds__(256)
void phase1(const float* __restrict__ ft, int N)
{
    const int n = blockIdx.x * 256 + threadIdx.x;
    if (n >= N) return;
    const float4* p = (const float4*)(ft + (size_t)n * FTOT);

    // two accumulator pairs for ILP on the lat-4 FFMA chains
    float xh0 = 0.f, xe0 = 0.f, xh1 = 0.f, xe1 = 0.f;

    {   // scalar-scalar terms: pl_ij = L2E * s_i*s_j via sqrt(L2E) pre-scale
        float s[C0];
#pragma unroll
        for (int q = 0; q < 8; ++q) {
            float4 t = __ldg(p + q);
            s[4*q+0] = t.x * SQRT_L2E; s[4*q+1] = t.y * SQRT_L2E;
            s[4*q+2] = t.z * SQRT_L2E; s[4*q+3] = t.w * SQRT_L2E;
        }
#pragma unroll
        for (int i = 0; i < C0; ++i)
#pragma unroll
            for (int j = i; j < C0; ++j) {
                float pl = s[i] * s[j];
                float w  = cW[KS(i, j)];              // uniform constant load
                if ((j ^ i) & 1) {
                    xh1 = fmaf(w, fmaxf(pl, 0.f), xh1);
                    xe1 = fmaf(w, ex2f(fminf(pl, 0.f)), xe1);
                } else {
                    xh0 = fmaf(w, fmaxf(pl, 0.f), xh0);
                    xe0 = fmaf(w, ex2f(fminf(pl, 0.f)), xe0);
                }
            }
    }
    {   // vector-vector terms: pl_ij = L2E * (v_i . v_j)/sqrt(3)
        float v[3 * C1];
#pragma unroll
        for (int q = 0; q < 12; ++q) {
            float4 t = __ldg(p + 8 + q);
            v[4*q+0] = t.x * SQRT_VL2E; v[4*q+1] = t.y * SQRT_VL2E;
            v[4*q+2] = t.z * SQRT_VL2E; v[4*q+3] = t.w * SQRT_VL2E;
        }
#pragma unroll
        for (int i = 0; i < C1; ++i)
#pragma unroll
            for (int j = i; j < C1; ++j) {
                float pl = v[3*i] * v[3*j];
                pl = fmaf(v[3*i+1], v[3*j+1], pl);
                pl = fmaf(v[3*i+2], v[3*j+2], pl);
                float w = cW[KV(i, j)];
                if ((j ^ i) & 1) {
                    xh1 = fmaf(w, fmaxf(pl, 0.f), xh1);
                    xe1 = fmaf(w, ex2f(fminf(pl, 0.f)), xe1);
                } else {
                    xh0 = fmaf(w, fmaxf(pl, 0.f), xh0);
                    xe0 = fmaf(w, ex2f(fminf(pl, 0.f)), xe0);
                }
            }
    }
    // unnormalized attention weight: exp(x) = ex2( SC*(xh + SA*L2E*xe) )
    float xh = xh0 + xh1, xe = xe0 + xe1;
    float earg = SELU_SCALE * fmaf(SELU_ALPHA * L2E, xe, xh);
    g_ex[n] = ex2f(earg);
}

// ---- phase 2: per-graph weighted segment sum + normalize ----
__global__ __launch_bounds__(256)
void phase2(const float* __restrict__ ft, const int* __restrict__ bidx,
            float* __restrict__ out, int N)
{
    __shared__ float s_acc[FTOT];
    __shared__ float s_z;
    __shared__ int   s_seg[2];

    const int tid  = threadIdx.x;
    const int wid  = tid >> 5;
    const int lane = tid & 31;
    const int g    = blockIdx.x;

    if (tid < FTOT) s_acc[tid] = 0.f;
    if (tid == 0)   s_z = 0.f;
    if (tid < 2) {
        int target = g + tid;
        int lo = 0, hi = N;
        while (lo < hi) {
            int mid = (lo + hi) >> 1;
            bool lt = (bidx[mid] < target);
            lo = lt ? mid + 1 : lo;
            hi = lt ? hi : mid;
        }
        s_seg[tid] = lo;
    }
    __syncthreads();
    const int start = s_seg[0], end = s_seg[1];

    float a0 = 0.f, a1 = 0.f, a2 = 0.f, zacc = 0.f;
    for (int n = start + wid; n < end; n += 8) {
        const float* p = ft + (size_t)n * FTOT;
        float ex = __ldg(&g_ex[n]);
        a0 = fmaf(ex, p[lane],      a0);
        a1 = fmaf(ex, p[lane + 32], a1);
        if (lane < 16) a2 = fmaf(ex, p[lane + 64], a2);
        zacc += ex;                 // same per lane; only lane0's copy is used
    }
    atomicAdd(&s_acc[lane],      a0);
    atomicAdd(&s_acc[lane + 32], a1);
    if (lane < 16) atomicAdd(&s_acc[lane + 64], a2);
    if (lane == 0) atomicAdd(&s_z, zacc);
    __syncthreads();

    float z   = s_z;
    float inv = (z != 0.f) ? (1.0f / z) : 0.f;   // empty graph -> zeros
    if (tid < FTOT) out[(size_t)g * FTOT + tid] = s_acc[tid] * inv;
}

extern "C" void kernel_launch(void* const* d_in, const int* in_sizes, int n_in,
                              void* d_out, int out_size)
{
    // node_ft: largest buffer; batch_index: size N int32; W: size 664.
    int ftIdx = -1; long ftSize = -1;
    for (int i = 0; i < n_in; ++i)
        if ((long)in_sizes[i] > ftSize) { ftSize = in_sizes[i]; ftIdx = i; }
    const int N = (int)(ftSize / FTOT);

    int biIdx = -1, wIdx = -1;
    for (int i = 0; i < n_in; ++i) {
        if (i == ftIdx) continue;
        if (in_sizes[i] == N)            biIdx = i;
        else if (in_sizes[i] == NTERMS)  wIdx = i;
    }

    const float* ft   = (const float*)d_in[ftIdx];
    const int*   bidx = (const int*)  d_in[biIdx];
    const float* W    = (const float*)d_in[wIdx];
    float*       out  = (float*)d_out;
    const int    NG   = out_size / FTOT;

    cudaMemcpyToSymbolAsync(cW, W, NTERMS * sizeof(float), 0,
                            cudaMemcpyDeviceToDevice, 0);
    phase1<<<(N + 255) / 256, 256>>>(ft, N);
    phase2<<<NG, 256>>>(ft, bidx, out, N);
}